// round 12
// baseline (speedup 1.0000x reference)
#include <cuda_runtime.h>
#include <cuda_bf16.h>
#include <cstdint>
#include <math.h>

// Problem constants
#define T_SEQ 4096
#define NB    2
#define C_EMB 512
#define NH    8
#define HD    64
#define BT    (NB * T_SEQ)   // 8192

// Scratch (static device globals; no allocation allowed)
__device__ __nv_bfloat16 g_xhi[(size_t)BT * C_EMB];          // x or y hi  [8192,512]
__device__ __nv_bfloat16 g_xlo[(size_t)BT * C_EMB];          // x or y lo
__device__ __nv_bfloat16 g_wa_hi[(size_t)3 * C_EMB * C_EMB]; // W_attn^T hi [1536,512]
__device__ __nv_bfloat16 g_wa_lo[(size_t)3 * C_EMB * C_EMB];
__device__ __nv_bfloat16 g_wp_hi[(size_t)C_EMB * C_EMB];     // W_proj^T hi [512,512]
__device__ __nv_bfloat16 g_wp_lo[(size_t)C_EMB * C_EMB];
// Head-major pre-split Q (scaled) / K / V: [b][h][t][d]
__device__ __nv_bfloat16 g_qhi[(size_t)BT * C_EMB];
__device__ __nv_bfloat16 g_qlo[(size_t)BT * C_EMB];
__device__ __nv_bfloat16 g_khi[(size_t)BT * C_EMB];
__device__ __nv_bfloat16 g_klo[(size_t)BT * C_EMB];
__device__ __nv_bfloat16 g_vhi[(size_t)BT * C_EMB];
__device__ __nv_bfloat16 g_vlo[(size_t)BT * C_EMB];

// ============================================================================
// PTX helpers (sm_80-era features only — plain sm_103 target safe)
// ============================================================================
__device__ __forceinline__ uint32_t smem_u32(const void* p) {
    uint32_t a;
    asm("{ .reg .u64 t; cvta.to.shared.u64 t, %1; cvt.u32.u64 %0, t; }"
        : "=r"(a) : "l"(p));
    return a;
}
__device__ __forceinline__ void ldm_x4(uint32_t addr, uint32_t& r0, uint32_t& r1,
                                       uint32_t& r2, uint32_t& r3) {
    asm volatile("ldmatrix.sync.aligned.m8n8.x4.shared.b16 {%0,%1,%2,%3}, [%4];"
                 : "=r"(r0), "=r"(r1), "=r"(r2), "=r"(r3) : "r"(addr));
}
__device__ __forceinline__ void ldm_x4t(uint32_t addr, uint32_t& r0, uint32_t& r1,
                                        uint32_t& r2, uint32_t& r3) {
    asm volatile("ldmatrix.sync.aligned.m8n8.x4.trans.shared.b16 {%0,%1,%2,%3}, [%4];"
                 : "=r"(r0), "=r"(r1), "=r"(r2), "=r"(r3) : "r"(addr));
}
__device__ __forceinline__ void mma_bf16(float* d, const uint32_t* a,
                                         uint32_t b0, uint32_t b1) {
    asm volatile(
        "mma.sync.aligned.m16n8k16.row.col.f32.bf16.bf16.f32 "
        "{%0,%1,%2,%3}, {%4,%5,%6,%7}, {%8,%9}, {%0,%1,%2,%3};"
        : "+f"(d[0]), "+f"(d[1]), "+f"(d[2]), "+f"(d[3])
        : "r"(a[0]), "r"(a[1]), "r"(a[2]), "r"(a[3]), "r"(b0), "r"(b1));
}
__device__ __forceinline__ uint32_t pack_bf16(float a, float b) {
    uint32_t r;
    asm("cvt.rn.bf16x2.f32 %0, %1, %2;" : "=r"(r) : "f"(b), "f"(a));
    return r;
}
__device__ __forceinline__ void split2(float x, float y, uint32_t& h, uint32_t& l) {
    h = pack_bf16(x, y);
    float xh = __uint_as_float((h & 0xFFFFu) << 16);
    float yh = __uint_as_float(h & 0xFFFF0000u);
    l = pack_bf16(x - xh, y - yh);
}
#define CP16(dst, src) \
    asm volatile("cp.async.cg.shared.global [%0], [%1], 16;" \
                 :: "r"(dst), "l"(src) : "memory")
#define CP_COMMIT() asm volatile("cp.async.commit_group;" ::: "memory")
#define CP_WAIT1()  asm volatile("cp.async.wait_group 1;" ::: "memory")
#define CP_WAIT0()  asm volatile("cp.async.wait_group 0;" ::: "memory")

// ============================================================================
// Fast exp on fma/alu pipes (no MUFU). Valid for x <= 0; ~2e-6 rel err.
// ============================================================================
__device__ __forceinline__ float fexp(float x) {
    float y = fmaxf(x * 1.44269504088896341f, -126.0f);
    float t = y + 12582912.0f;
    int   n = __float_as_int(t) - 0x4B400000;
    float f = y - (t - 12582912.0f);
    float p = fmaf(f, 0.0013333558f, 0.0096181291f);
    p = fmaf(f, p, 0.0555041087f);
    p = fmaf(f, p, 0.2402264791f);
    p = fmaf(f, p, 0.6931472028f);
    p = fmaf(f, p, 1.0f);
    return __int_as_float(__float_as_int(p) + (n << 23));
}

// ============================================================================
// Prep kernels
// ============================================================================
__global__ __launch_bounds__(256) void convert_split(
    const float* __restrict__ src, __nv_bfloat16* __restrict__ hi,
    __nv_bfloat16* __restrict__ lo, int n4)
{
    int i = blockIdx.x * 256 + threadIdx.x;
    if (i >= n4) return;
    float4 v = ((const float4*)src)[i];
    uint32_t h0, l0, h1, l1;
    split2(v.x, v.y, h0, l0);
    split2(v.z, v.w, h1, l1);
    ((uint2*)hi)[i] = make_uint2(h0, h1);
    ((uint2*)lo)[i] = make_uint2(l0, l1);
}

// W [K,N] row-major -> Wt hi/lo [N,K] (K-major) bf16 split. grid (N/32, K/32).
__global__ __launch_bounds__(256) void convert_wT(
    const float* __restrict__ W, __nv_bfloat16* __restrict__ Thi,
    __nv_bfloat16* __restrict__ Tlo, int K, int N)
{
    __shared__ float tile[32][33];
    const int bx = blockIdx.x * 32, by = blockIdx.y * 32;
    const int tx = threadIdx.x & 31, ty = threadIdx.x >> 5;
    #pragma unroll
    for (int i = 0; i < 4; i++) {
        int r = ty + i * 8;
        tile[r][tx] = W[(size_t)(by + r) * N + bx + tx];
    }
    __syncthreads();
    #pragma unroll
    for (int i = 0; i < 4; i++) {
        int r = ty + i * 8;
        float v = tile[tx][r];
        __nv_bfloat16 h = __float2bfloat16(v);
        __nv_bfloat16 l = __float2bfloat16(v - __bfloat162float(h));
        size_t o = (size_t)(bx + r) * K + by + tx;
        Thi[o] = h; Tlo[o] = l;
    }
}

// ============================================================================
// GEMM core macro-pieces shared by both GEMM kernels.
// ============================================================================
#define GK_TOT 512
#define GBK    32
#define SROW   40                    // halves per smem row (80 B)
#define GTILE  (128 * SROW * 2)      // 10240 B per tile
#define GSTAGE (4 * GTILE)           // 40960 B per stage

// Computes acc for one 128x128 block of A[M,512] @ B[N,512]^T (hi/lo 3-term).
// Defines/uses: smem(extern), t, wid, lane, m0, n0, wm0, wn0, acc.
#define GEMM_MAINLOOP(Ahi, Alo, Bhi, Blo)                                      \
    const uint32_t sb = smem_u32(smem);                                        \
    const uint32_t aoff = ((uint32_t)(lane & 15) * SROW + (lane >> 4) * 8) * 2;\
    const uint32_t boff = ((uint32_t)(((lane >> 4) & 1) * 8 + (lane & 7)) * SROW \
                          + ((lane >> 3) & 1) * 8) * 2;                        \
    auto prefetch = [&](int ch, int s) {                                       \
        _Pragma("unroll")                                                      \
        for (int i = 0; i < 8; i++) {                                          \
            int u   = t + i * 256;                                             \
            int arr = u >> 9;                                                  \
            int rem = u & 511;                                                 \
            int r   = rem >> 2;                                                \
            int c8  = (rem & 3) * 8;                                           \
            uint32_t dst = sb + s * GSTAGE + arr * GTILE                       \
                         + (uint32_t)(r * SROW + c8) * 2;                      \
            const __nv_bfloat16* gp =                                          \
                (arr == 0) ? Ahi + (size_t)(m0 + r) * GK_TOT :                 \
                (arr == 1) ? Alo + (size_t)(m0 + r) * GK_TOT :                 \
                (arr == 2) ? Bhi + (size_t)(n0 + r) * GK_TOT :                 \
                             Blo + (size_t)(n0 + r) * GK_TOT;                  \
            CP16(dst, gp + ch * GBK + c8);                                     \
        }                                                                      \
    };                                                                         \
    prefetch(0, 0);                                                            \
    CP_COMMIT();                                                               \
    for (int ch = 0; ch < GK_TOT / GBK; ch++) {                                \
        const int cs = ch & 1;                                                 \
        if (ch < GK_TOT / GBK - 1) {                                           \
            prefetch(ch + 1, cs ^ 1);                                          \
            CP_COMMIT();                                                       \
            CP_WAIT1();                                                        \
        } else {                                                               \
            CP_WAIT0();                                                        \
        }                                                                      \
        __syncthreads();                                                       \
        const uint32_t sAhi = sb + cs * GSTAGE;                                \
        const uint32_t sAlo = sAhi + GTILE;                                    \
        const uint32_t sBhi = sAhi + 2 * GTILE;                                \
        const uint32_t sBlo = sAhi + 3 * GTILE;                                \
        _Pragma("unroll")                                                      \
        for (int ks = 0; ks < 2; ks++) {                                       \
            const uint32_t kb = ks * 16 * 2;                                   \
            uint32_t ah[4][4], al[4][4], bh[2][4], bl[2][4];                   \
            _Pragma("unroll")                                                  \
            for (int mt = 0; mt < 4; mt++) {                                   \
                uint32_t ra = (uint32_t)((wm0 + mt * 16) * SROW) * 2 + aoff + kb; \
                ldm_x4(sAhi + ra, ah[mt][0], ah[mt][1], ah[mt][2], ah[mt][3]); \
                ldm_x4(sAlo + ra, al[mt][0], al[mt][1], al[mt][2], al[mt][3]); \
            }                                                                  \
            _Pragma("unroll")                                                  \
            for (int np = 0; np < 2; np++) {                                   \
                uint32_t rb = (uint32_t)((wn0 + np * 16) * SROW) * 2 + boff + kb; \
                ldm_x4(sBhi + rb, bh[np][0], bh[np][1], bh[np][2], bh[np][3]); \
                ldm_x4(sBlo + rb, bl[np][0], bl[np][1], bl[np][2], bl[np][3]); \
            }                                                                  \
            _Pragma("unroll")                                                  \
            for (int mt = 0; mt < 4; mt++)                                     \
                _Pragma("unroll")                                              \
                for (int nt = 0; nt < 4; nt++) {                               \
                    uint32_t h0 = bh[nt >> 1][(nt & 1) * 2];                   \
                    uint32_t h1 = bh[nt >> 1][(nt & 1) * 2 + 1];               \
                    uint32_t l0 = bl[nt >> 1][(nt & 1) * 2];                   \
                    uint32_t l1 = bl[nt >> 1][(nt & 1) * 2 + 1];               \
                    mma_bf16(acc[mt][nt], ah[mt], h0, h1);                     \
                    mma_bf16(acc[mt][nt], ah[mt], l0, l1);                     \
                    mma_bf16(acc[mt][nt], al[mt], h0, h1);                     \
                }                                                              \
        }                                                                      \
        __syncthreads();                                                       \
    }

// ---- generic GEMM: fp32 C out (used for the output projection) ----
__global__ __launch_bounds__(256) void mma_gemm(
    const __nv_bfloat16* __restrict__ Ahi, const __nv_bfloat16* __restrict__ Alo,
    const __nv_bfloat16* __restrict__ Bhi, const __nv_bfloat16* __restrict__ Blo,
    float* __restrict__ C, int M, int N)
{
    extern __shared__ char smem[];
    const int t    = threadIdx.x;
    const int wid  = t >> 5;
    const int lane = t & 31;
    const int m0   = blockIdx.y * 128;
    const int n0   = blockIdx.x * 128;
    const int wm0  = (wid & 1) * 64;
    const int wn0  = (wid >> 1) * 32;

    float acc[4][4][4];
    #pragma unroll
    for (int i = 0; i < 4; i++)
        #pragma unroll
        for (int j = 0; j < 4; j++)
            #pragma unroll
            for (int k = 0; k < 4; k++) acc[i][j][k] = 0.f;

    GEMM_MAINLOOP(Ahi, Alo, Bhi, Blo)

    const int g  = lane >> 2;
    const int cq = (lane & 3) * 2;
    #pragma unroll
    for (int mt = 0; mt < 4; mt++)
        #pragma unroll
        for (int nt = 0; nt < 4; nt++) {
            float* cp = C + (size_t)(m0 + wm0 + mt * 16 + g) * N
                          + n0 + wn0 + nt * 8 + cq;
            *(float2*)cp = make_float2(acc[mt][nt][0], acc[mt][nt][1]);
            *(float2*)(cp + (size_t)8 * N) = make_float2(acc[mt][nt][2], acc[mt][nt][3]);
        }
}

// ---- QKV GEMM: writes head-major bf16 hi/lo Q(scaled)/K/V directly ----
__global__ __launch_bounds__(256) void mma_gemm_qkv(
    const __nv_bfloat16* __restrict__ Ahi, const __nv_bfloat16* __restrict__ Alo,
    const __nv_bfloat16* __restrict__ Bhi, const __nv_bfloat16* __restrict__ Blo,
    __nv_bfloat16* __restrict__ qhi, __nv_bfloat16* __restrict__ qlo,
    __nv_bfloat16* __restrict__ khi, __nv_bfloat16* __restrict__ klo,
    __nv_bfloat16* __restrict__ vhi, __nv_bfloat16* __restrict__ vlo)
{
    extern __shared__ char smem[];
    const int t    = threadIdx.x;
    const int wid  = t >> 5;
    const int lane = t & 31;
    const int m0   = blockIdx.y * 128;
    const int n0   = blockIdx.x * 128;    // N = 1536
    const int wm0  = (wid & 1) * 64;
    const int wn0  = (wid >> 1) * 32;

    float acc[4][4][4];
    #pragma unroll
    for (int i = 0; i < 4; i++)
        #pragma unroll
        for (int j = 0; j < 4; j++)
            #pragma unroll
            for (int k = 0; k < 4; k++) acc[i][j][k] = 0.f;

    GEMM_MAINLOOP(Ahi, Alo, Bhi, Blo)

    // epilogue: split + scatter to [b][h][t][64]
    const int g  = lane >> 2;
    const int cq = (lane & 3) * 2;
    const int region = n0 >> 9;                      // 0=q, 1=k, 2=v (uniform/block)
    const float scale = (region == 0) ? 0.125f : 1.0f;
    __nv_bfloat16* Hp = (region == 0) ? qhi : (region == 1) ? khi : vhi;
    __nv_bfloat16* Lp = (region == 0) ? qlo : (region == 1) ? klo : vlo;

    #pragma unroll
    for (int mt = 0; mt < 4; mt++) {
        int r  = m0 + wm0 + mt * 16 + g;             // rows r, r+8
        int b  = r >> 12;
        int t0 = r & (T_SEQ - 1);
        #pragma unroll
        for (int nt = 0; nt < 4; nt++) {
            int c  = (n0 & 511) + wn0 + nt * 8 + cq; // 0..511 within region
            int h  = c >> 6;
            int d  = c & 63;
            size_t base = (((size_t)(b * NH + h)) * T_SEQ + t0) * HD + d;
            uint32_t hh, ll;
            split2(acc[mt][nt][0] * scale, acc[mt][nt][1] * scale, hh, ll);
            *(uint32_t*)(Hp + base) = hh;
            *(uint32_t*)(Lp + base) = ll;
            split2(acc[mt][nt][2] * scale, acc[mt][nt][3] * scale, hh, ll);
            *(uint32_t*)(Hp + base + (size_t)8 * HD) = hh;
            *(uint32_t*)(Lp + base + (size_t)8 * HD) = ll;
        }
    }
}

// ============================================================================
// Flash attention: mma.sync, pre-split head-major bf16 Q/K/V, cp.async double
// buffer, 2 CTAs/SM. Writes y directly as bf16 hi/lo split (proj A operand).
// ============================================================================
#define SRA    72                    // halves per smem row (144 B)
#define ATILE  (64 * SRA * 2)        // 9216 B per K/V array tile
#define ASTAGE (4 * ATILE)           // 36864 B per stage

__global__ __launch_bounds__(256, 2) void attn_mma_kernel(
    const __nv_bfloat16* __restrict__ qhi, const __nv_bfloat16* __restrict__ qlo,
    const __nv_bfloat16* __restrict__ khi, const __nv_bfloat16* __restrict__ klo,
    const __nv_bfloat16* __restrict__ vhi, const __nv_bfloat16* __restrict__ vlo,
    __nv_bfloat16* __restrict__ yhi, __nv_bfloat16* __restrict__ ylo)
{
    extern __shared__ char smem[];
    const uint32_t sb = smem_u32(smem);

    const int t    = threadIdx.x;
    const int w    = t >> 5;
    const int lane = t & 31;
    const int qt   = gridDim.x - 1 - blockIdx.x;   // heavy tiles first
    const int bh   = blockIdx.y;
    const int b    = bh >> 3;
    const int h    = bh & 7;

    const size_t hb = ((size_t)(b * NH + h)) << 18;
    const __nv_bfloat16* Kh = khi + hb;
    const __nv_bfloat16* Kl = klo + hb;
    const __nv_bfloat16* Vh = vhi + hb;
    const __nv_bfloat16* Vl = vlo + hb;

    auto prefetch = [&](int jt, int s) {
        #pragma unroll
        for (int i = 0; i < 8; i++) {
            int u   = t + i * 256;
            int arr = u >> 9;
            int rem = u & 511;
            int r   = rem >> 3;
            int c8  = (rem & 7) * 8;
            uint32_t dst = sb + s * ASTAGE + arr * ATILE
                         + (uint32_t)(r * SRA + c8) * 2;
            const __nv_bfloat16* gp = (arr == 0) ? Kh : (arr == 1) ? Kl
                                    : (arr == 2) ? Vh : Vl;
            CP16(dst, gp + ((size_t)(jt * 64 + r) << 6) + c8);
        }
    };

    prefetch(0, 0);
    CP_COMMIT();

    // ---- stage Q tile into stage-1 area, extract frags to registers ----
    {
        const __nv_bfloat16* Qh = qhi + hb + ((size_t)qt * 128 << 6);
        const __nv_bfloat16* Ql = qlo + hb + ((size_t)qt * 128 << 6);
        #pragma unroll
        for (int i = 0; i < 8; i++) {
            int u   = t + i * 256;
            int arr = u >> 10;
            int rem = u & 1023;
            int r   = rem >> 3;
            int c8  = (rem & 7) * 8;
            const __nv_bfloat16* gp = arr ? Ql : Qh;
            *(uint4*)(smem + ASTAGE + arr * (128 * SRA * 2)
                      + (uint32_t)(r * SRA + c8) * 2) =
                *(const uint4*)(gp + (r << 6) + c8);
        }
    }
    __syncthreads();

    const uint32_t aoff = ((uint32_t)(lane & 15) * SRA + (lane >> 4) * 8) * 2;
    const uint32_t boff = ((uint32_t)(((lane >> 4) & 1) * 8 + (lane & 7)) * SRA
                          + ((lane >> 3) & 1) * 8) * 2;
    const uint32_t voff = ((uint32_t)(((lane >> 3) & 1) * 8 + (lane & 7)) * SRA
                          + (lane >> 4) * 8) * 2;

    uint32_t qh[4][4], ql[4][4];
    {
        const uint32_t QHI = sb + ASTAGE, QLO = QHI + 128 * SRA * 2;
        #pragma unroll
        for (int kt = 0; kt < 4; kt++) {
            uint32_t ra = (uint32_t)(w * 16 * SRA + kt * 16) * 2 + aoff;
            ldm_x4(QHI + ra, qh[kt][0], qh[kt][1], qh[kt][2], qh[kt][3]);
            ldm_x4(QLO + ra, ql[kt][0], ql[kt][1], ql[kt][2], ql[kt][3]);
        }
    }
    __syncthreads();

    const int g   = lane >> 2;
    const int cq  = (lane & 3) * 2;
    const int row0 = qt * 128 + w * 16 + g;

    float m0 = -1e30f, m1 = -1e30f, l0 = 0.f, l1 = 0.f;
    float o[8][4];
    #pragma unroll
    for (int i = 0; i < 8; i++)
        #pragma unroll
        for (int j = 0; j < 4; j++) o[i][j] = 0.f;

    const int jt_max = 2 * qt + 1;
    for (int jt = 0; jt <= jt_max; jt++) {
        const int cs = jt & 1;
        if (jt < jt_max) {
            prefetch(jt + 1, cs ^ 1);
            CP_COMMIT();
            CP_WAIT1();
        } else {
            CP_WAIT0();
        }
        __syncthreads();

        const uint32_t SKH = sb + cs * ASTAGE;
        const uint32_t SKL = SKH + ATILE;
        const uint32_t SVH = SKH + 2 * ATILE;
        const uint32_t SVL = SKH + 3 * ATILE;

        // ---- S = Q @ K^T ----
        float s[8][4];
        #pragma unroll
        for (int i = 0; i < 8; i++)
            #pragma unroll
            for (int j = 0; j < 4; j++) s[i][j] = 0.f;

        #pragma unroll
        for (int kt = 0; kt < 4; kt++) {
            #pragma unroll
            for (int np = 0; np < 4; np++) {
                uint32_t kh4[4], kl4[4];
                uint32_t rb = (uint32_t)(np * 16 * SRA + kt * 16) * 2 + boff;
                ldm_x4(SKH + rb, kh4[0], kh4[1], kh4[2], kh4[3]);
                ldm_x4(SKL + rb, kl4[0], kl4[1], kl4[2], kl4[3]);
                #pragma unroll
                for (int qn = 0; qn < 2; qn++) {
                    int nt = np * 2 + qn;
                    mma_bf16(s[nt], qh[kt], kh4[qn * 2], kh4[qn * 2 + 1]);
                    mma_bf16(s[nt], qh[kt], kl4[qn * 2], kl4[qn * 2 + 1]);
                    mma_bf16(s[nt], ql[kt], kh4[qn * 2], kh4[qn * 2 + 1]);
                }
            }
        }

        // ---- causal mask (straddling tiles only) ----
        if (jt >= 2 * qt) {
            #pragma unroll
            for (int nt = 0; nt < 8; nt++) {
                int col = jt * 64 + nt * 8 + cq;
                if (col     > row0)     s[nt][0] = -1e30f;
                if (col + 1 > row0)     s[nt][1] = -1e30f;
                if (col     > row0 + 8) s[nt][2] = -1e30f;
                if (col + 1 > row0 + 8) s[nt][3] = -1e30f;
            }
        }

        // ---- online softmax ----
        float mx0 = -1e30f, mx1 = -1e30f;
        #pragma unroll
        for (int nt = 0; nt < 8; nt++) {
            mx0 = fmaxf(mx0, fmaxf(s[nt][0], s[nt][1]));
            mx1 = fmaxf(mx1, fmaxf(s[nt][2], s[nt][3]));
        }
        mx0 = fmaxf(mx0, __shfl_xor_sync(0xffffffffu, mx0, 1));
        mx0 = fmaxf(mx0, __shfl_xor_sync(0xffffffffu, mx0, 2));
        mx1 = fmaxf(mx1, __shfl_xor_sync(0xffffffffu, mx1, 1));
        mx1 = fmaxf(mx1, __shfl_xor_sync(0xffffffffu, mx1, 2));
        float mn0 = fmaxf(m0, mx0), mn1 = fmaxf(m1, mx1);
        float a0 = fexp(m0 - mn0), a1 = fexp(m1 - mn1);
        m0 = mn0; m1 = mn1;
        float rs0 = 0.f, rs1 = 0.f;
        #pragma unroll
        for (int nt = 0; nt < 8; nt++) {
            s[nt][0] = fexp(s[nt][0] - mn0);
            s[nt][1] = fexp(s[nt][1] - mn0);
            s[nt][2] = fexp(s[nt][2] - mn1);
            s[nt][3] = fexp(s[nt][3] - mn1);
            rs0 += s[nt][0] + s[nt][1];
            rs1 += s[nt][2] + s[nt][3];
        }
        rs0 += __shfl_xor_sync(0xffffffffu, rs0, 1);
        rs0 += __shfl_xor_sync(0xffffffffu, rs0, 2);
        rs1 += __shfl_xor_sync(0xffffffffu, rs1, 1);
        rs1 += __shfl_xor_sync(0xffffffffu, rs1, 2);
        l0 = l0 * a0 + rs0;
        l1 = l1 * a1 + rs1;
        if (!__all_sync(0xffffffffu, (a0 == 1.f) & (a1 == 1.f))) {
            #pragma unroll
            for (int dt = 0; dt < 8; dt++) {
                o[dt][0] *= a0; o[dt][1] *= a0;
                o[dt][2] *= a1; o[dt][3] *= a1;
            }
        }

        // ---- O += P @ V ----
        #pragma unroll
        for (int kt = 0; kt < 4; kt++) {
            uint32_t ph[4], pl[4];
            split2(s[2 * kt][0],     s[2 * kt][1],     ph[0], pl[0]);
            split2(s[2 * kt][2],     s[2 * kt][3],     ph[1], pl[1]);
            split2(s[2 * kt + 1][0], s[2 * kt + 1][1], ph[2], pl[2]);
            split2(s[2 * kt + 1][2], s[2 * kt + 1][3], ph[3], pl[3]);
            #pragma unroll
            for (int dn = 0; dn < 4; dn++) {
                uint32_t vh4[4], vl4[4];
                uint32_t rv = (uint32_t)(kt * 16 * SRA + dn * 16) * 2 + voff;
                ldm_x4t(SVH + rv, vh4[0], vh4[1], vh4[2], vh4[3]);
                ldm_x4t(SVL + rv, vl4[0], vl4[1], vl4[2], vl4[3]);
                #pragma unroll
                for (int qn = 0; qn < 2; qn++) {
                    int dt = dn * 2 + qn;
                    mma_bf16(o[dt], ph, vh4[qn * 2], vh4[qn * 2 + 1]);
                    mma_bf16(o[dt], ph, vl4[qn * 2], vl4[qn * 2 + 1]);
                    mma_bf16(o[dt], pl, vh4[qn * 2], vh4[qn * 2 + 1]);
                }
            }
        }
        __syncthreads();
    }

    // ---- epilogue: normalize and write y split (proj A operand layout) ----
    const float inv0 = 1.f / l0, inv1 = 1.f / l1;
    const size_t base = ((size_t)b * T_SEQ + row0) * C_EMB + h * HD;
    #pragma unroll
    for (int dt = 0; dt < 8; dt++) {
        size_t off = base + dt * 8 + cq;
        uint32_t hh, ll;
        split2(o[dt][0] * inv0, o[dt][1] * inv0, hh, ll);
        *(uint32_t*)(yhi + off) = hh;
        *(uint32_t*)(ylo + off) = ll;
        split2(o[dt][2] * inv1, o[dt][3] * inv1, hh, ll);
        *(uint32_t*)(yhi + off + (size_t)8 * C_EMB) = hh;
        *(uint32_t*)(ylo + off + (size_t)8 * C_EMB) = ll;
    }
}

// ============================================================================
extern "C" void kernel_launch(void* const* d_in, const int* in_sizes, int n_in,
                              void* d_out, int out_size)
{
    const float* x      = (const float*)d_in[0];
    const float* W_attn = (const float*)d_in[1];
    const float* W_proj = (const float*)d_in[2];
    float* out = (float*)d_out;

    __nv_bfloat16 *xhi, *xlo, *wahi, *walo, *wphi, *wplo;
    __nv_bfloat16 *qhi, *qlo, *khi, *klo, *vhi, *vlo;
    cudaGetSymbolAddress((void**)&xhi, g_xhi);
    cudaGetSymbolAddress((void**)&xlo, g_xlo);
    cudaGetSymbolAddress((void**)&wahi, g_wa_hi);
    cudaGetSymbolAddress((void**)&walo, g_wa_lo);
    cudaGetSymbolAddress((void**)&wphi, g_wp_hi);
    cudaGetSymbolAddress((void**)&wplo, g_wp_lo);
    cudaGetSymbolAddress((void**)&qhi, g_qhi);
    cudaGetSymbolAddress((void**)&qlo, g_qlo);
    cudaGetSymbolAddress((void**)&khi, g_khi);
    cudaGetSymbolAddress((void**)&klo, g_klo);
    cudaGetSymbolAddress((void**)&vhi, g_vhi);
    cudaGetSymbolAddress((void**)&vlo, g_vlo);

    const int smem_attn = 2 * ASTAGE;    // 73,728 B
    const int smem_gemm = 2 * GSTAGE;    // 81,920 B
    static int attr_set = 0;
    if (!attr_set) {
        cudaFuncSetAttribute(attn_mma_kernel,
                             cudaFuncAttributeMaxDynamicSharedMemorySize, smem_attn);
        cudaFuncSetAttribute(mma_gemm,
                             cudaFuncAttributeMaxDynamicSharedMemorySize, smem_gemm);
        cudaFuncSetAttribute(mma_gemm_qkv,
                             cudaFuncAttributeMaxDynamicSharedMemorySize, smem_gemm);
        attr_set = 1;
    }

    // Prep: weights transposed+split (K-major), x split
    convert_wT<<<dim3(3 * C_EMB / 32, C_EMB / 32), 256>>>(W_attn, wahi, walo, C_EMB, 3 * C_EMB);
    convert_wT<<<dim3(C_EMB / 32, C_EMB / 32), 256>>>(W_proj, wphi, wplo, C_EMB, C_EMB);
    convert_split<<<(BT * C_EMB / 4 + 255) / 256, 256>>>(x, xhi, xlo, BT * C_EMB / 4);

    // 1) qkv = x @ W_attn, fused split to head-major bf16 hi/lo (Q pre-scaled)
    mma_gemm_qkv<<<dim3(3 * C_EMB / 128, BT / 128), 256, smem_gemm>>>(
        xhi, xlo, wahi, walo, qhi, qlo, khi, klo, vhi, vlo);

    // 2) causal attention; writes y directly as bf16 hi/lo split
    attn_mma_kernel<<<dim3(T_SEQ / 128, NB * NH), 256, smem_attn>>>(
        qhi, qlo, khi, klo, vhi, vlo, xhi, xlo);

    // 3) out = y @ W_proj
    mma_gemm<<<dim3(C_EMB / 128, BT / 128), 256, smem_gemm>>>(
        xhi, xlo, wphi, wplo, out, BT, C_EMB);
}

// round 15
// speedup vs baseline: 1.0891x; 1.0891x over previous
#include <cuda_runtime.h>
#include <cuda_bf16.h>
#include <cstdint>
#include <math.h>

// Problem constants
#define T_SEQ 4096
#define NB    2
#define C_EMB 512
#define NH    8
#define HD    64
#define BT    (NB * T_SEQ)   // 8192

// Scratch (static device globals; no allocation allowed)
__device__ __nv_bfloat16 g_xhi[(size_t)BT * C_EMB];          // x or y hi  [8192,512]
__device__ __nv_bfloat16 g_xlo[(size_t)BT * C_EMB];          // x or y lo
__device__ __nv_bfloat16 g_wa_hi[(size_t)3 * C_EMB * C_EMB]; // W_attn^T hi [1536,512]
__device__ __nv_bfloat16 g_wa_lo[(size_t)3 * C_EMB * C_EMB];
__device__ __nv_bfloat16 g_wp_hi[(size_t)C_EMB * C_EMB];     // W_proj^T hi [512,512]
__device__ __nv_bfloat16 g_wp_lo[(size_t)C_EMB * C_EMB];
// Head-major pre-split Q (scaled) / K / V: [b][h][t][d]
__device__ __nv_bfloat16 g_qhi[(size_t)BT * C_EMB];
__device__ __nv_bfloat16 g_qlo[(size_t)BT * C_EMB];
__device__ __nv_bfloat16 g_khi[(size_t)BT * C_EMB];
__device__ __nv_bfloat16 g_klo[(size_t)BT * C_EMB];
__device__ __nv_bfloat16 g_vhi[(size_t)BT * C_EMB];
__device__ __nv_bfloat16 g_vlo[(size_t)BT * C_EMB];

// ============================================================================
// PTX helpers (sm_80-era features only — plain sm_103 target safe)
// ============================================================================
__device__ __forceinline__ uint32_t smem_u32(const void* p) {
    uint32_t a;
    asm("{ .reg .u64 t; cvta.to.shared.u64 t, %1; cvt.u32.u64 %0, t; }"
        : "=r"(a) : "l"(p));
    return a;
}
__device__ __forceinline__ void ldm_x4(uint32_t addr, uint32_t& r0, uint32_t& r1,
                                       uint32_t& r2, uint32_t& r3) {
    asm volatile("ldmatrix.sync.aligned.m8n8.x4.shared.b16 {%0,%1,%2,%3}, [%4];"
                 : "=r"(r0), "=r"(r1), "=r"(r2), "=r"(r3) : "r"(addr));
}
__device__ __forceinline__ void ldm_x4t(uint32_t addr, uint32_t& r0, uint32_t& r1,
                                        uint32_t& r2, uint32_t& r3) {
    asm volatile("ldmatrix.sync.aligned.m8n8.x4.trans.shared.b16 {%0,%1,%2,%3}, [%4];"
                 : "=r"(r0), "=r"(r1), "=r"(r2), "=r"(r3) : "r"(addr));
}
__device__ __forceinline__ void mma_bf16(float* d, const uint32_t* a,
                                         uint32_t b0, uint32_t b1) {
    asm volatile(
        "mma.sync.aligned.m16n8k16.row.col.f32.bf16.bf16.f32 "
        "{%0,%1,%2,%3}, {%4,%5,%6,%7}, {%8,%9}, {%0,%1,%2,%3};"
        : "+f"(d[0]), "+f"(d[1]), "+f"(d[2]), "+f"(d[3])
        : "r"(a[0]), "r"(a[1]), "r"(a[2]), "r"(a[3]), "r"(b0), "r"(b1));
}
__device__ __forceinline__ uint32_t pack_bf16(float a, float b) {
    uint32_t r;
    asm("cvt.rn.bf16x2.f32 %0, %1, %2;" : "=r"(r) : "f"(b), "f"(a));
    return r;
}
__device__ __forceinline__ void split2(float x, float y, uint32_t& h, uint32_t& l) {
    h = pack_bf16(x, y);
    float xh = __uint_as_float((h & 0xFFFFu) << 16);
    float yh = __uint_as_float(h & 0xFFFF0000u);
    l = pack_bf16(x - xh, y - yh);
}
#define CP16(dst, src) \
    asm volatile("cp.async.cg.shared.global [%0], [%1], 16;" \
                 :: "r"(dst), "l"(src) : "memory")
#define CP_COMMIT() asm volatile("cp.async.commit_group;" ::: "memory")
#define CP_WAIT1()  asm volatile("cp.async.wait_group 1;" ::: "memory")
#define CP_WAIT0()  asm volatile("cp.async.wait_group 0;" ::: "memory")

// ============================================================================
// Fast exp on fma/alu pipes (no MUFU). Valid for x <= 0; ~2e-6 rel err.
// ============================================================================
__device__ __forceinline__ float fexp(float x) {
    float y = fmaxf(x * 1.44269504088896341f, -126.0f);
    float t = y + 12582912.0f;
    int   n = __float_as_int(t) - 0x4B400000;
    float f = y - (t - 12582912.0f);
    float p = fmaf(f, 0.0013333558f, 0.0096181291f);
    p = fmaf(f, p, 0.0555041087f);
    p = fmaf(f, p, 0.2402264791f);
    p = fmaf(f, p, 0.6931472028f);
    p = fmaf(f, p, 1.0f);
    return __int_as_float(__float_as_int(p) + (n << 23));
}

// ============================================================================
// Prep kernels
// ============================================================================
__global__ __launch_bounds__(256) void convert_split(
    const float* __restrict__ src, __nv_bfloat16* __restrict__ hi,
    __nv_bfloat16* __restrict__ lo, int n4)
{
    int i = blockIdx.x * 256 + threadIdx.x;
    if (i >= n4) return;
    float4 v = ((const float4*)src)[i];
    uint32_t h0, l0, h1, l1;
    split2(v.x, v.y, h0, l0);
    split2(v.z, v.w, h1, l1);
    ((uint2*)hi)[i] = make_uint2(h0, h1);
    ((uint2*)lo)[i] = make_uint2(l0, l1);
}

// W [K,N] row-major -> Wt hi/lo [N,K] (K-major) bf16 split. grid (N/32, K/32).
__global__ __launch_bounds__(256) void convert_wT(
    const float* __restrict__ W, __nv_bfloat16* __restrict__ Thi,
    __nv_bfloat16* __restrict__ Tlo, int K, int N)
{
    __shared__ float tile[32][33];
    const int bx = blockIdx.x * 32, by = blockIdx.y * 32;
    const int tx = threadIdx.x & 31, ty = threadIdx.x >> 5;
    #pragma unroll
    for (int i = 0; i < 4; i++) {
        int r = ty + i * 8;
        tile[r][tx] = W[(size_t)(by + r) * N + bx + tx];
    }
    __syncthreads();
    #pragma unroll
    for (int i = 0; i < 4; i++) {
        int r = ty + i * 8;
        float v = tile[tx][r];
        __nv_bfloat16 h = __float2bfloat16(v);
        __nv_bfloat16 l = __float2bfloat16(v - __bfloat162float(h));
        size_t o = (size_t)(bx + r) * K + by + tx;
        Thi[o] = h; Tlo[o] = l;
    }
}

// ============================================================================
// GEMM core macro-pieces shared by both GEMM kernels.
// ============================================================================
#define GK_TOT 512
#define GBK    32
#define SROW   40                    // halves per smem row (80 B)
#define GTILE  (128 * SROW * 2)      // 10240 B per tile
#define GSTAGE (4 * GTILE)           // 40960 B per stage

// Computes acc for one 128x128 block of A[M,512] @ B[N,512]^T (hi/lo 3-term).
// Defines/uses: smem(extern), t, wid, lane, m0, n0, wm0, wn0, acc.
#define GEMM_MAINLOOP(Ahi, Alo, Bhi, Blo)                                      \
    const uint32_t sb = smem_u32(smem);                                        \
    const uint32_t aoff = ((uint32_t)(lane & 15) * SROW + (lane >> 4) * 8) * 2;\
    const uint32_t boff = ((uint32_t)(((lane >> 4) & 1) * 8 + (lane & 7)) * SROW \
                          + ((lane >> 3) & 1) * 8) * 2;                        \
    auto prefetch = [&](int ch, int s) {                                       \
        _Pragma("unroll")                                                      \
        for (int i = 0; i < 8; i++) {                                          \
            int u   = t + i * 256;                                             \
            int arr = u >> 9;                                                  \
            int rem = u & 511;                                                 \
            int r   = rem >> 2;                                                \
            int c8  = (rem & 3) * 8;                                           \
            uint32_t dst = sb + s * GSTAGE + arr * GTILE                       \
                         + (uint32_t)(r * SROW + c8) * 2;                      \
            const __nv_bfloat16* gp =                                          \
                (arr == 0) ? Ahi + (size_t)(m0 + r) * GK_TOT :                 \
                (arr == 1) ? Alo + (size_t)(m0 + r) * GK_TOT :                 \
                (arr == 2) ? Bhi + (size_t)(n0 + r) * GK_TOT :                 \
                             Blo + (size_t)(n0 + r) * GK_TOT;                  \
            CP16(dst, gp + ch * GBK + c8);                                     \
        }                                                                      \
    };                                                                         \
    prefetch(0, 0);                                                            \
    CP_COMMIT();                                                               \
    for (int ch = 0; ch < GK_TOT / GBK; ch++) {                                \
        const int cs = ch & 1;                                                 \
        if (ch < GK_TOT / GBK - 1) {                                           \
            prefetch(ch + 1, cs ^ 1);                                          \
            CP_COMMIT();                                                       \
            CP_WAIT1();                                                        \
        } else {                                                               \
            CP_WAIT0();                                                        \
        }                                                                      \
        __syncthreads();                                                       \
        const uint32_t sAhi = sb + cs * GSTAGE;                                \
        const uint32_t sAlo = sAhi + GTILE;                                    \
        const uint32_t sBhi = sAhi + 2 * GTILE;                                \
        const uint32_t sBlo = sAhi + 3 * GTILE;                                \
        _Pragma("unroll")                                                      \
        for (int ks = 0; ks < 2; ks++) {                                       \
            const uint32_t kb = ks * 16 * 2;                                   \
            uint32_t ah[4][4], al[4][4], bh[2][4], bl[2][4];                   \
            _Pragma("unroll")                                                  \
            for (int mt = 0; mt < 4; mt++) {                                   \
                uint32_t ra = (uint32_t)((wm0 + mt * 16) * SROW) * 2 + aoff + kb; \
                ldm_x4(sAhi + ra, ah[mt][0], ah[mt][1], ah[mt][2], ah[mt][3]); \
                ldm_x4(sAlo + ra, al[mt][0], al[mt][1], al[mt][2], al[mt][3]); \
            }                                                                  \
            _Pragma("unroll")                                                  \
            for (int np = 0; np < 2; np++) {                                   \
                uint32_t rb = (uint32_t)((wn0 + np * 16) * SROW) * 2 + boff + kb; \
                ldm_x4(sBhi + rb, bh[np][0], bh[np][1], bh[np][2], bh[np][3]); \
                ldm_x4(sBlo + rb, bl[np][0], bl[np][1], bl[np][2], bl[np][3]); \
            }                                                                  \
            _Pragma("unroll")                                                  \
            for (int mt = 0; mt < 4; mt++)                                     \
                _Pragma("unroll")                                              \
                for (int nt = 0; nt < 4; nt++) {                               \
                    uint32_t h0 = bh[nt >> 1][(nt & 1) * 2];                   \
                    uint32_t h1 = bh[nt >> 1][(nt & 1) * 2 + 1];               \
                    uint32_t l0 = bl[nt >> 1][(nt & 1) * 2];                   \
                    uint32_t l1 = bl[nt >> 1][(nt & 1) * 2 + 1];               \
                    mma_bf16(acc[mt][nt], ah[mt], h0, h1);                     \
                    mma_bf16(acc[mt][nt], ah[mt], l0, l1);                     \
                    mma_bf16(acc[mt][nt], al[mt], h0, h1);                     \
                }                                                              \
        }                                                                      \
        __syncthreads();                                                       \
    }

// ---- generic GEMM: fp32 C out (used for the output projection) ----
__global__ __launch_bounds__(256) void mma_gemm(
    const __nv_bfloat16* __restrict__ Ahi, const __nv_bfloat16* __restrict__ Alo,
    const __nv_bfloat16* __restrict__ Bhi, const __nv_bfloat16* __restrict__ Blo,
    float* __restrict__ C, int M, int N)
{
    extern __shared__ char smem[];
    const int t    = threadIdx.x;
    const int wid  = t >> 5;
    const int lane = t & 31;
    const int m0   = blockIdx.y * 128;
    const int n0   = blockIdx.x * 128;
    const int wm0  = (wid & 1) * 64;
    const int wn0  = (wid >> 1) * 32;

    float acc[4][4][4];
    #pragma unroll
    for (int i = 0; i < 4; i++)
        #pragma unroll
        for (int j = 0; j < 4; j++)
            #pragma unroll
            for (int k = 0; k < 4; k++) acc[i][j][k] = 0.f;

    GEMM_MAINLOOP(Ahi, Alo, Bhi, Blo)

    const int g  = lane >> 2;
    const int cq = (lane & 3) * 2;
    #pragma unroll
    for (int mt = 0; mt < 4; mt++)
        #pragma unroll
        for (int nt = 0; nt < 4; nt++) {
            float* cp = C + (size_t)(m0 + wm0 + mt * 16 + g) * N
                          + n0 + wn0 + nt * 8 + cq;
            *(float2*)cp = make_float2(acc[mt][nt][0], acc[mt][nt][1]);
            *(float2*)(cp + (size_t)8 * N) = make_float2(acc[mt][nt][2], acc[mt][nt][3]);
        }
}

// ---- QKV GEMM: writes head-major bf16 hi/lo Q(scaled)/K/V directly ----
__global__ __launch_bounds__(256) void mma_gemm_qkv(
    const __nv_bfloat16* __restrict__ Ahi, const __nv_bfloat16* __restrict__ Alo,
    const __nv_bfloat16* __restrict__ Bhi, const __nv_bfloat16* __restrict__ Blo,
    __nv_bfloat16* __restrict__ qhi, __nv_bfloat16* __restrict__ qlo,
    __nv_bfloat16* __restrict__ khi, __nv_bfloat16* __restrict__ klo,
    __nv_bfloat16* __restrict__ vhi, __nv_bfloat16* __restrict__ vlo)
{
    extern __shared__ char smem[];
    const int t    = threadIdx.x;
    const int wid  = t >> 5;
    const int lane = t & 31;
    const int m0   = blockIdx.y * 128;
    const int n0   = blockIdx.x * 128;    // N = 1536
    const int wm0  = (wid & 1) * 64;
    const int wn0  = (wid >> 1) * 32;

    float acc[4][4][4];
    #pragma unroll
    for (int i = 0; i < 4; i++)
        #pragma unroll
        for (int j = 0; j < 4; j++)
            #pragma unroll
            for (int k = 0; k < 4; k++) acc[i][j][k] = 0.f;

    GEMM_MAINLOOP(Ahi, Alo, Bhi, Blo)

    // epilogue: split + scatter to [b][h][t][64]
    const int g  = lane >> 2;
    const int cq = (lane & 3) * 2;
    const int region = n0 >> 9;                      // 0=q, 1=k, 2=v (uniform/block)
    const float scale = (region == 0) ? 0.125f : 1.0f;
    __nv_bfloat16* Hp = (region == 0) ? qhi : (region == 1) ? khi : vhi;
    __nv_bfloat16* Lp = (region == 0) ? qlo : (region == 1) ? klo : vlo;

    #pragma unroll
    for (int mt = 0; mt < 4; mt++) {
        int r  = m0 + wm0 + mt * 16 + g;             // rows r, r+8
        int b  = r >> 12;
        int t0 = r & (T_SEQ - 1);
        #pragma unroll
        for (int nt = 0; nt < 4; nt++) {
            int c  = (n0 & 511) + wn0 + nt * 8 + cq; // 0..511 within region
            int h  = c >> 6;
            int d  = c & 63;
            size_t base = (((size_t)(b * NH + h)) * T_SEQ + t0) * HD + d;
            uint32_t hh, ll;
            split2(acc[mt][nt][0] * scale, acc[mt][nt][1] * scale, hh, ll);
            *(uint32_t*)(Hp + base) = hh;
            *(uint32_t*)(Lp + base) = ll;
            split2(acc[mt][nt][2] * scale, acc[mt][nt][3] * scale, hh, ll);
            *(uint32_t*)(Hp + base + (size_t)8 * HD) = hh;
            *(uint32_t*)(Lp + base + (size_t)8 * HD) = ll;
        }
    }
}

// ============================================================================
// Flash attention: mma.sync, pre-split head-major bf16 Q/K/V, cp.async double
// buffer. 1 CTA/SM (no reg cap — spills cost more than co-residency buys).
// Writes y directly as bf16 hi/lo split (proj A operand).
// ============================================================================
#define SRA    72                    // halves per smem row (144 B)
#define ATILE  (64 * SRA * 2)        // 9216 B per K/V array tile
#define ASTAGE (4 * ATILE)           // 36864 B per stage

__global__ __launch_bounds__(256) void attn_mma_kernel(
    const __nv_bfloat16* __restrict__ qhi, const __nv_bfloat16* __restrict__ qlo,
    const __nv_bfloat16* __restrict__ khi, const __nv_bfloat16* __restrict__ klo,
    const __nv_bfloat16* __restrict__ vhi, const __nv_bfloat16* __restrict__ vlo,
    __nv_bfloat16* __restrict__ yhi, __nv_bfloat16* __restrict__ ylo)
{
    extern __shared__ char smem[];
    const uint32_t sb = smem_u32(smem);

    const int t    = threadIdx.x;
    const int w    = t >> 5;
    const int lane = t & 31;
    const int qt   = gridDim.x - 1 - blockIdx.x;   // heavy tiles first
    const int bh   = blockIdx.y;
    const int b    = bh >> 3;
    const int h    = bh & 7;

    const size_t hb = ((size_t)(b * NH + h)) << 18;
    const __nv_bfloat16* Kh = khi + hb;
    const __nv_bfloat16* Kl = klo + hb;
    const __nv_bfloat16* Vh = vhi + hb;
    const __nv_bfloat16* Vl = vlo + hb;

    auto prefetch = [&](int jt, int s) {
        #pragma unroll
        for (int i = 0; i < 8; i++) {
            int u   = t + i * 256;
            int arr = u >> 9;
            int rem = u & 511;
            int r   = rem >> 3;
            int c8  = (rem & 7) * 8;
            uint32_t dst = sb + s * ASTAGE + arr * ATILE
                         + (uint32_t)(r * SRA + c8) * 2;
            const __nv_bfloat16* gp = (arr == 0) ? Kh : (arr == 1) ? Kl
                                    : (arr == 2) ? Vh : Vl;
            CP16(dst, gp + ((size_t)(jt * 64 + r) << 6) + c8);
        }
    };

    prefetch(0, 0);
    CP_COMMIT();

    // ---- stage Q tile into stage-1 area, extract frags to registers ----
    {
        const __nv_bfloat16* Qh = qhi + hb + ((size_t)qt * 128 << 6);
        const __nv_bfloat16* Ql = qlo + hb + ((size_t)qt * 128 << 6);
        #pragma unroll
        for (int i = 0; i < 8; i++) {
            int u   = t + i * 256;
            int arr = u >> 10;
            int rem = u & 1023;
            int r   = rem >> 3;
            int c8  = (rem & 7) * 8;
            const __nv_bfloat16* gp = arr ? Ql : Qh;
            *(uint4*)(smem + ASTAGE + arr * (128 * SRA * 2)
                      + (uint32_t)(r * SRA + c8) * 2) =
                *(const uint4*)(gp + (r << 6) + c8);
        }
    }
    __syncthreads();

    const uint32_t aoff = ((uint32_t)(lane & 15) * SRA + (lane >> 4) * 8) * 2;
    const uint32_t boff = ((uint32_t)(((lane >> 4) & 1) * 8 + (lane & 7)) * SRA
                          + ((lane >> 3) & 1) * 8) * 2;
    const uint32_t voff = ((uint32_t)(((lane >> 3) & 1) * 8 + (lane & 7)) * SRA
                          + (lane >> 4) * 8) * 2;

    uint32_t qh[4][4], ql[4][4];
    {
        const uint32_t QHI = sb + ASTAGE, QLO = QHI + 128 * SRA * 2;
        #pragma unroll
        for (int kt = 0; kt < 4; kt++) {
            uint32_t ra = (uint32_t)(w * 16 * SRA + kt * 16) * 2 + aoff;
            ldm_x4(QHI + ra, qh[kt][0], qh[kt][1], qh[kt][2], qh[kt][3]);
            ldm_x4(QLO + ra, ql[kt][0], ql[kt][1], ql[kt][2], ql[kt][3]);
        }
    }
    __syncthreads();

    const int g   = lane >> 2;
    const int cq  = (lane & 3) * 2;
    const int row0 = qt * 128 + w * 16 + g;

    float m0 = -1e30f, m1 = -1e30f, l0 = 0.f, l1 = 0.f;
    float o[8][4];
    #pragma unroll
    for (int i = 0; i < 8; i++)
        #pragma unroll
        for (int j = 0; j < 4; j++) o[i][j] = 0.f;

    const int jt_max = 2 * qt + 1;
    for (int jt = 0; jt <= jt_max; jt++) {
        const int cs = jt & 1;
        if (jt < jt_max) {
            prefetch(jt + 1, cs ^ 1);
            CP_COMMIT();
            CP_WAIT1();
        } else {
            CP_WAIT0();
        }
        __syncthreads();

        const uint32_t SKH = sb + cs * ASTAGE;
        const uint32_t SKL = SKH + ATILE;
        const uint32_t SVH = SKH + 2 * ATILE;
        const uint32_t SVL = SKH + 3 * ATILE;

        // ---- S = Q @ K^T ----
        float s[8][4];
        #pragma unroll
        for (int i = 0; i < 8; i++)
            #pragma unroll
            for (int j = 0; j < 4; j++) s[i][j] = 0.f;

        #pragma unroll
        for (int kt = 0; kt < 4; kt++) {
            #pragma unroll
            for (int np = 0; np < 4; np++) {
                uint32_t kh4[4], kl4[4];
                uint32_t rb = (uint32_t)(np * 16 * SRA + kt * 16) * 2 + boff;
                ldm_x4(SKH + rb, kh4[0], kh4[1], kh4[2], kh4[3]);
                ldm_x4(SKL + rb, kl4[0], kl4[1], kl4[2], kl4[3]);
                #pragma unroll
                for (int qn = 0; qn < 2; qn++) {
                    int nt = np * 2 + qn;
                    mma_bf16(s[nt], qh[kt], kh4[qn * 2], kh4[qn * 2 + 1]);
                    mma_bf16(s[nt], qh[kt], kl4[qn * 2], kl4[qn * 2 + 1]);
                    mma_bf16(s[nt], ql[kt], kh4[qn * 2], kh4[qn * 2 + 1]);
                }
            }
        }

        // ---- causal mask (straddling tiles only) ----
        if (jt >= 2 * qt) {
            #pragma unroll
            for (int nt = 0; nt < 8; nt++) {
                int col = jt * 64 + nt * 8 + cq;
                if (col     > row0)     s[nt][0] = -1e30f;
                if (col + 1 > row0)     s[nt][1] = -1e30f;
                if (col     > row0 + 8) s[nt][2] = -1e30f;
                if (col + 1 > row0 + 8) s[nt][3] = -1e30f;
            }
        }

        // ---- online softmax ----
        float mx0 = -1e30f, mx1 = -1e30f;
        #pragma unroll
        for (int nt = 0; nt < 8; nt++) {
            mx0 = fmaxf(mx0, fmaxf(s[nt][0], s[nt][1]));
            mx1 = fmaxf(mx1, fmaxf(s[nt][2], s[nt][3]));
        }
        mx0 = fmaxf(mx0, __shfl_xor_sync(0xffffffffu, mx0, 1));
        mx0 = fmaxf(mx0, __shfl_xor_sync(0xffffffffu, mx0, 2));
        mx1 = fmaxf(mx1, __shfl_xor_sync(0xffffffffu, mx1, 1));
        mx1 = fmaxf(mx1, __shfl_xor_sync(0xffffffffu, mx1, 2));
        float mn0 = fmaxf(m0, mx0), mn1 = fmaxf(m1, mx1);
        float a0 = fexp(m0 - mn0), a1 = fexp(m1 - mn1);
        m0 = mn0; m1 = mn1;
        float rs0 = 0.f, rs1 = 0.f;
        #pragma unroll
        for (int nt = 0; nt < 8; nt++) {
            s[nt][0] = fexp(s[nt][0] - mn0);
            s[nt][1] = fexp(s[nt][1] - mn0);
            s[nt][2] = fexp(s[nt][2] - mn1);
            s[nt][3] = fexp(s[nt][3] - mn1);
            rs0 += s[nt][0] + s[nt][1];
            rs1 += s[nt][2] + s[nt][3];
        }
        rs0 += __shfl_xor_sync(0xffffffffu, rs0, 1);
        rs0 += __shfl_xor_sync(0xffffffffu, rs0, 2);
        rs1 += __shfl_xor_sync(0xffffffffu, rs1, 1);
        rs1 += __shfl_xor_sync(0xffffffffu, rs1, 2);
        l0 = l0 * a0 + rs0;
        l1 = l1 * a1 + rs1;
        if (!__all_sync(0xffffffffu, (a0 == 1.f) & (a1 == 1.f))) {
            #pragma unroll
            for (int dt = 0; dt < 8; dt++) {
                o[dt][0] *= a0; o[dt][1] *= a0;
                o[dt][2] *= a1; o[dt][3] *= a1;
            }
        }

        // ---- O += P @ V ----
        #pragma unroll
        for (int kt = 0; kt < 4; kt++) {
            uint32_t ph[4], pl[4];
            split2(s[2 * kt][0],     s[2 * kt][1],     ph[0], pl[0]);
            split2(s[2 * kt][2],     s[2 * kt][3],     ph[1], pl[1]);
            split2(s[2 * kt + 1][0], s[2 * kt + 1][1], ph[2], pl[2]);
            split2(s[2 * kt + 1][2], s[2 * kt + 1][3], ph[3], pl[3]);
            #pragma unroll
            for (int dn = 0; dn < 4; dn++) {
                uint32_t vh4[4], vl4[4];
                uint32_t rv = (uint32_t)(kt * 16 * SRA + dn * 16) * 2 + voff;
                ldm_x4t(SVH + rv, vh4[0], vh4[1], vh4[2], vh4[3]);
                ldm_x4t(SVL + rv, vl4[0], vl4[1], vl4[2], vl4[3]);
                #pragma unroll
                for (int qn = 0; qn < 2; qn++) {
                    int dt = dn * 2 + qn;
                    mma_bf16(o[dt], ph, vh4[qn * 2], vh4[qn * 2 + 1]);
                    mma_bf16(o[dt], ph, vl4[qn * 2], vl4[qn * 2 + 1]);
                    mma_bf16(o[dt], pl, vh4[qn * 2], vh4[qn * 2 + 1]);
                }
            }
        }
        __syncthreads();
    }

    // ---- epilogue: normalize and write y split (proj A operand layout) ----
    const float inv0 = 1.f / l0, inv1 = 1.f / l1;
    const size_t base = ((size_t)b * T_SEQ + row0) * C_EMB + h * HD;
    #pragma unroll
    for (int dt = 0; dt < 8; dt++) {
        size_t off = base + dt * 8 + cq;
        uint32_t hh, ll;
        split2(o[dt][0] * inv0, o[dt][1] * inv0, hh, ll);
        *(uint32_t*)(yhi + off) = hh;
        *(uint32_t*)(ylo + off) = ll;
        split2(o[dt][2] * inv1, o[dt][3] * inv1, hh, ll);
        *(uint32_t*)(yhi + off + (size_t)8 * C_EMB) = hh;
        *(uint32_t*)(ylo + off + (size_t)8 * C_EMB) = ll;
    }
}

// ============================================================================
extern "C" void kernel_launch(void* const* d_in, const int* in_sizes, int n_in,
                              void* d_out, int out_size)
{
    const float* x      = (const float*)d_in[0];
    const float* W_attn = (const float*)d_in[1];
    const float* W_proj = (const float*)d_in[2];
    float* out = (float*)d_out;

    __nv_bfloat16 *xhi, *xlo, *wahi, *walo, *wphi, *wplo;
    __nv_bfloat16 *qhi, *qlo, *khi, *klo, *vhi, *vlo;
    cudaGetSymbolAddress((void**)&xhi, g_xhi);
    cudaGetSymbolAddress((void**)&xlo, g_xlo);
    cudaGetSymbolAddress((void**)&wahi, g_wa_hi);
    cudaGetSymbolAddress((void**)&walo, g_wa_lo);
    cudaGetSymbolAddress((void**)&wphi, g_wp_hi);
    cudaGetSymbolAddress((void**)&wplo, g_wp_lo);
    cudaGetSymbolAddress((void**)&qhi, g_qhi);
    cudaGetSymbolAddress((void**)&qlo, g_qlo);
    cudaGetSymbolAddress((void**)&khi, g_khi);
    cudaGetSymbolAddress((void**)&klo, g_klo);
    cudaGetSymbolAddress((void**)&vhi, g_vhi);
    cudaGetSymbolAddress((void**)&vlo, g_vlo);

    const int smem_attn = 2 * ASTAGE;    // 73,728 B
    const int smem_gemm = 2 * GSTAGE;    // 81,920 B
    static int attr_set = 0;
    if (!attr_set) {
        cudaFuncSetAttribute(attn_mma_kernel,
                             cudaFuncAttributeMaxDynamicSharedMemorySize, smem_attn);
        cudaFuncSetAttribute(mma_gemm,
                             cudaFuncAttributeMaxDynamicSharedMemorySize, smem_gemm);
        cudaFuncSetAttribute(mma_gemm_qkv,
                             cudaFuncAttributeMaxDynamicSharedMemorySize, smem_gemm);
        attr_set = 1;
    }

    // Prep: weights transposed+split (K-major), x split
    convert_wT<<<dim3(3 * C_EMB / 32, C_EMB / 32), 256>>>(W_attn, wahi, walo, C_EMB, 3 * C_EMB);
    convert_wT<<<dim3(C_EMB / 32, C_EMB / 32), 256>>>(W_proj, wphi, wplo, C_EMB, C_EMB);
    convert_split<<<(BT * C_EMB / 4 + 255) / 256, 256>>>(x, xhi, xlo, BT * C_EMB / 4);

    // 1) qkv = x @ W_attn, fused split to head-major bf16 hi/lo (Q pre-scaled)
    mma_gemm_qkv<<<dim3(3 * C_EMB / 128, BT / 128), 256, smem_gemm>>>(
        xhi, xlo, wahi, walo, qhi, qlo, khi, klo, vhi, vlo);

    // 2) causal attention; writes y directly as bf16 hi/lo split
    attn_mma_kernel<<<dim3(T_SEQ / 128, NB * NH), 256, smem_attn>>>(
        qhi, qlo, khi, klo, vhi, vlo, xhi, xlo);

    // 3) out = y @ W_proj
    mma_gemm<<<dim3(C_EMB / 128, BT / 128), 256, smem_gemm>>>(
        xhi, xlo, wphi, wplo, out, BT, C_EMB);
}